// round 8
// baseline (speedup 1.0000x reference)
#include <cuda_runtime.h>
#include <cstdint>
#include <math.h>

// Problem constants (fixed by the reference)
#define T_STEPS 250
#define NCH     3
#define DFEAT   40
#define IN_DIM  120     // NCH*DFEAT
#define NHID    200
#define NBR     8
#define NBRT    4       // branches per producer thread (2 threads per neuron)
#define PER     15      // IN_DIM / NBR
#define PERP    16      // padded per-branch stride in xbuf
#define XPAD    (NBR*PERP)   // 128
#define ODIM    35
#define NB      4       // batch elements per CTA
#define THREADS 512
#define NPROD   416     // warps 0..12 = producers (neurons + x ingest)
#define NCONS   96      // warps 13..15 = consumers (readout + integrator)
#define NSLOTS  (NB*ODIM)    // 140 (batch, output) readout slots
#define W2PAD   212     // W2 row stride: 8 rows/warp spread over all 32 banks

// branch k -> xbuf slot (even/odd lane halves land in disjoint bank groups)
#define BSLOT(k) (2 * ((k) & 3) + ((k) >> 2))

// named barriers: 1+p = spikes[p] FULL, 3+p = spikes[p] FREE, 5 = producer-only
#define BAR_SYNC(id, cnt)   asm volatile("bar.sync %0, %1;"   :: "r"(id), "r"(cnt) : "memory")
#define BAR_ARRIVE(id, cnt) asm volatile("bar.arrive %0, %1;" :: "r"(id), "r"(cnt) : "memory")

// ---------------- packed f32x2 helpers (sm_100a) ----------------
__device__ __forceinline__ unsigned long long ffma2(unsigned long long a,
                                                    unsigned long long b,
                                                    unsigned long long c) {
    unsigned long long d;
    asm("fma.rn.f32x2 %0, %1, %2, %3;" : "=l"(d) : "l"(a), "l"(b), "l"(c));
    return d;
}
__device__ __forceinline__ unsigned long long add2(unsigned long long a,
                                                   unsigned long long b) {
    unsigned long long d;
    asm("add.rn.f32x2 %0, %1, %2;" : "=l"(d) : "l"(a), "l"(b));
    return d;
}
__device__ __forceinline__ unsigned long long pack2(float lo, float hi) {
    unsigned long long u;
    asm("mov.b64 %0, {%1, %2};" : "=l"(u) : "f"(lo), "f"(hi));
    return u;
}
__device__ __forceinline__ float2 unpack2(unsigned long long u) {
    float lo, hi;
    asm("mov.b64 {%0, %1}, %2;" : "=f"(lo), "=f"(hi) : "l"(u));
    return make_float2(lo, hi);
}
__device__ __forceinline__ float sigmoid_acc(float v) {
    return 1.0f / (1.0f + expf(-v));
}

// Warp-specialized pipelined SNN. One CTA = 4 batch elements; grid 128 = one
// wave. Producers (13 warps) run the LIF neuron recurrence; consumers (3
// warps) run readout+integration one step behind on double-buffered spikes.
__global__ void __launch_bounds__(THREADS, 1) snn_kernel(
    const float* __restrict__ x,       // [B, 3, 250, 40]
    const float* __restrict__ W1,      // [200, 8, 120]
    const float* __restrict__ b1,      // [200]
    const float* __restrict__ tau_m1,  // [200]
    const float* __restrict__ tau_n1,  // [200, 8]
    const float* __restrict__ W2,      // [35, 200]
    const float* __restrict__ b2,      // [35]
    const float* __restrict__ tau_m2,  // [35]
    float* __restrict__ out,           // [B, 35]
    int B)
{
    __shared__ __align__(16) float xbuf[2][NB][XPAD];   // double-buffered xt
    __shared__ __align__(16) float spk_s[2][NB][NHID];  // double-buffered spikes
    __shared__ __align__(16) float w2s[ODIM][W2PAD];    // W2 rows, bank-spread
    __shared__ float accbuf[NB][ODIM];                  // integrator results

    const int tid = threadIdx.x;
    const int b0  = blockIdx.x * NB;

    // ---- one-time: W2 rows into SMEM (all threads) ----
    for (int idx = tid; idx < ODIM * NHID; idx += THREADS) {
        const int o = idx / NHID, n = idx % NHID;
        w2s[o][n] = W2[o * NHID + n];
    }
    __syncthreads();   // w2s ready before consumers use it

    if (tid < NPROD) {
        // ======================= PRODUCER =======================
        const int h   = tid & 1;            // branch half
        const int nn0 = tid >> 1;           // neuron id (valid < 200)
        const int ncl = (nn0 < NHID) ? nn0 : NHID - 1;

        unsigned long long wp[NBRT * 7];
        float w14[NBRT], beta[NBRT];
        float dst[NB][NBRT];
        float mem1[NB], spk[NB];
#pragma unroll
        for (int bl = 0; bl < NB; bl++) {
            mem1[bl] = 0.f; spk[bl] = 0.f;
#pragma unroll
            for (int kk = 0; kk < NBRT; kk++) dst[bl][kk] = 0.f;
        }
        const float alpha1 = sigmoid_acc(tau_m1[ncl]);
        const float oma1   = 1.0f - alpha1;
        const float b1n    = b1[ncl];
#pragma unroll
        for (int kk = 0; kk < NBRT; kk++) {
            const int k = 4 * h + kk;
            beta[kk] = sigmoid_acc(tau_n1[ncl * NBR + k]);
            const float* wrow = W1 + (size_t)(ncl * NBR + k) * IN_DIM + k * PER;
#pragma unroll
            for (int j = 0; j < 7; j++)
                wp[kk * 7 + j] = pack2(wrow[2 * j], wrow[2 * j + 1]);
            w14[kk] = wrow[14];
        }

        // x ingest: element e1 = tid (always), e2 = 416+tid for tid<64
        float* const xb = &xbuf[0][0][0];
        const int e1   = tid;
        const int bl1  = e1 / IN_DIM, i1 = e1 % IN_DIM;
        int bb1 = b0 + bl1; if (bb1 > B - 1) bb1 = B - 1;
        const float* pf1 = x + ((size_t)bb1 * NCH + i1 / DFEAT) * T_STEPS * DFEAT
                             + (i1 % DFEAT);
        const int of1 = bl1 * XPAD + BSLOT(i1 / PER) * PERP + (i1 % PER);
        const bool two = (tid < NB * IN_DIM - NPROD);       // tid < 64
        const int e2  = NPROD + tid;
        const int bl2 = e2 / IN_DIM, i2 = e2 % IN_DIM;      // bl2 == 3
        int bb2 = b0 + bl2; if (bb2 > B - 1) bb2 = B - 1;
        const float* pf2 = x + ((size_t)bb2 * NCH + i2 / DFEAT) * T_STEPS * DFEAT
                             + (i2 % DFEAT);
        const int of2 = bl2 * XPAD + BSLOT(i2 / PER) * PERP + (i2 % PER);

        // pre-scatter t=0 into buffer 0, then stage x(1)
        float xr1 = pf1[0];
        float xr2 = two ? pf2[0] : 0.f;
        xb[of1] = xr1;
        if (two) xb[of2] = xr2;
        BAR_SYNC(5, NPROD);
        xr1 = pf1[DFEAT];
        if (two) xr2 = pf2[DFEAT];

#pragma unroll 1
        for (int t = 0; t < T_STEPS; t++) {
            const int p = t & 1;
            if (t >= 2) BAR_SYNC(3 + p, THREADS);   // spikes[p] free (consumer t-2 done)

            const float* xbp = &xbuf[p][0][0];
#pragma unroll
            for (int bl = 0; bl < NB; bl++) {
                float lh = 0.f;
#pragma unroll
                for (int kk = 0; kk < NBRT; kk++) {
                    const ulonglong2* xp =
                        (const ulonglong2*)(xbp + bl * XPAD + (2 * kk + h) * PERP);
                    ulonglong2 q0 = xp[0];
                    ulonglong2 q1 = xp[1];
                    unsigned long long a0, a1;
                    a0 = ffma2(wp[kk * 7 + 0], q0.x, 0ull);
                    a1 = ffma2(wp[kk * 7 + 1], q0.y, 0ull);
                    a0 = ffma2(wp[kk * 7 + 2], q1.x, a0);
                    a1 = ffma2(wp[kk * 7 + 3], q1.y, a1);
                    ulonglong2 q2 = xp[2];
                    a0 = ffma2(wp[kk * 7 + 4], q2.x, a0);
                    a1 = ffma2(wp[kk * 7 + 5], q2.y, a1);
                    ulonglong2 q3 = xp[3];
                    a0 = ffma2(wp[kk * 7 + 6], q3.x, a0);
                    float2 vv = unpack2(add2(a0, a1));
                    float2 hx = unpack2(q3.y);            // (x14, pad-unused)
                    float  I  = fmaf(w14[kk], hx.x, vv.x + vv.y);
                    float  dk = dst[bl][kk];
                    dk = fmaf(beta[kk], dk - I, I);       // beta*d + (1-beta)*I
                    dst[bl][kk] = dk;
                    lh += dk;
                }
                const float l = lh + __shfl_xor_sync(0xFFFFFFFFu, lh, 1) + b1n;
                float m = fmaf(alpha1, mem1[bl] - spk[bl], oma1 * l);
                mem1[bl] = m;
                float s = (m > 1.0f) ? 1.0f : 0.0f;
                spk[bl] = s;
                if (h == 0 && nn0 < NHID) spk_s[p][bl][nn0] = s;
            }
            __threadfence_block();          // order STS before arrive
            BAR_ARRIVE(1 + p, THREADS);     // spikes[p] full

            if (t < T_STEPS - 1) {
                // scatter x(t+1) into the other buffer; stage x(t+2)
                float* xbn = &xbuf[p ^ 1][0][0];
                xbn[of1] = xr1;
                if (two) xbn[of2] = xr2;
                BAR_SYNC(5, NPROD);
                const int tn = (t + 2 < T_STEPS) ? t + 2 : T_STEPS - 1;
                xr1 = pf1[(size_t)tn * DFEAT];
                if (two) xr2 = pf2[(size_t)tn * DFEAT];
            }
        }
    } else {
        // ======================= CONSUMER =======================
        const int c  = tid - NPROD;                 // 0..95
        const int sA = c;                           // slot A (< 140 always)
        const int sB = (c + NCONS < NSLOTS) ? c + NCONS : c;   // slot B (dup ok)
        const int blA = sA % NB, oA = sA / NB;
        const int blB = sB % NB, oB = sB / NB;
        const float alpha2A = sigmoid_acc(tau_m2[oA]);
        const float oma2A   = 1.0f - alpha2A;
        const float b2A     = b2[oA];
        const float alpha2B = sigmoid_acc(tau_m2[oB]);
        const float oma2B   = 1.0f - alpha2B;
        const float b2B     = b2[oB];
        float mem2A = 0.f, accA = 0.f, mem2B = 0.f, accB = 0.f;

        const ulonglong2* const wA = (const ulonglong2*)&w2s[oA][0];
        const ulonglong2* const wB = (const ulonglong2*)&w2s[oB][0];

#pragma unroll 1
        for (int t = 0; t < T_STEPS; t++) {
            const int p = t & 1;
            BAR_SYNC(1 + p, THREADS);               // spikes[p] full (fences)

            const ulonglong2* sAp = (const ulonglong2*)&spk_s[p][blA][0];
            const ulonglong2* sBp = (const ulonglong2*)&spk_s[p][blB][0];
            unsigned long long a0 = 0ull, a1 = 0ull, c0 = 0ull, c1 = 0ull;
            // NHID/4 = 50 iterations: each ulonglong2 covers 4 floats
#pragma unroll 10
            for (int j = 0; j < NHID / 4; j++) {
                ulonglong2 wv = wA[j];
                ulonglong2 sv = sAp[j];
                a0 = ffma2(wv.x, sv.x, a0);
                a1 = ffma2(wv.y, sv.y, a1);
                wv = wB[j];
                sv = sBp[j];
                c0 = ffma2(wv.x, sv.x, c0);
                c1 = ffma2(wv.y, sv.y, c1);
            }
            if (t < T_STEPS - 2) BAR_ARRIVE(3 + p, THREADS);   // spikes[p] free

            float2 dA = unpack2(add2(a0, a1));
            float  zA = dA.x + dA.y + b2A;
            mem2A = fmaf(alpha2A, mem2A, oma2A * zA);
            accA += mem2A;
            float2 dB = unpack2(add2(c0, c1));
            float  zB = dB.x + dB.y + b2B;
            mem2B = fmaf(alpha2B, mem2B, oma2B * zB);
            accB += mem2B;
        }
        accbuf[blA][oA] = accA * (1.0f / (float)T_STEPS);
        if (sB != sA) accbuf[blB][oB] = accB * (1.0f / (float)T_STEPS);
    }

    __syncthreads();

    // ==================== epilogue: log_softmax ====================
    if (tid < NSLOTS) {
        const int bl = tid / ODIM, o = tid % ODIM;
        const int b  = b0 + bl;
        if (b < B) {
            float m = -INFINITY;
#pragma unroll
            for (int j = 0; j < ODIM; j++) m = fmaxf(m, accbuf[bl][j]);
            float ssum = 0.0f;
#pragma unroll
            for (int j = 0; j < ODIM; j++) ssum += expf(accbuf[bl][j] - m);
            out[(size_t)b * ODIM + o] = accbuf[bl][o] - m - logf(ssum);
        }
    }
}

extern "C" void kernel_launch(void* const* d_in, const int* in_sizes, int n_in,
                              void* d_out, int out_size) {
    const float* x      = (const float*)d_in[0];
    const float* W1     = (const float*)d_in[1];
    const float* b1     = (const float*)d_in[2];
    const float* tau_m1 = (const float*)d_in[3];
    const float* tau_n1 = (const float*)d_in[4];
    const float* W2     = (const float*)d_in[5];
    const float* b2     = (const float*)d_in[6];
    const float* tau_m2 = (const float*)d_in[7];
    float* out = (float*)d_out;

    const int B = in_sizes[0] / (NCH * T_STEPS * DFEAT);   // 512
    const int grid = (B + NB - 1) / NB;                    // 128
    snn_kernel<<<grid, THREADS>>>(x, W1, b1, tau_m1, tau_n1, W2, b2, tau_m2,
                                  out, B);
}